// round 1
// baseline (speedup 1.0000x reference)
#include <cuda_runtime.h>

// db2 inverse DWT (synthesis), polyphase form.
// x: [32, 512, 512, 4] NHWC f32  ->  y: [32, 1024, 1024, 1] f32
//
// y[b, 2s+av, 2t+ah] = sum_{c,dv,dh} Fh_c[av][dv] * Fw_c[ah][dh] * x[b, min(s+dv,511), min(t+dh,511), c]
// with Fh/Fw per channel: c0,c1 -> (lpf,lpf); c2 -> (lpf,hpf); c3 -> (hpf,hpf)
// and for a 4-tap filter f: F[0] = {f[1], f[3]}, F[1] = {f[0], f[2]}.

#define IN_H 512
#define IN_W 512
#define IN_B 32

__global__ __launch_bounds__(128)
void idwt_db2_kernel(const float* __restrict__ x, float* __restrict__ y) {
    const int t = blockIdx.x * blockDim.x + threadIdx.x;   // 0..511 (input col)
    const int s = blockIdx.y;                              // 0..511 (input row)
    const int b = blockIdx.z;                              // 0..31

    // db2 coefficients
    const float h0 = 0.48296291314469025f;
    const float h1 = 0.83651630373780790f;
    const float h2 = 0.22414386804185735f;
    const float h3 = -0.12940952255092145f;

    // lpf = {h3, h2, h1, h0}  -> L[0]={h2,h0}, L[1]={h3,h1}
    // hpf = {-h0, h1, -h2, h3}-> G[0]={h1,h3}, G[1]={-h0,-h2}
    const float L[2][2] = { { h2,  h0 }, {  h3,  h1 } };
    const float G[2][2] = { { h1,  h3 }, { -h0, -h2 } };

    const int t1 = min(t + 1, IN_W - 1);
    const int s1 = min(s + 1, IN_H - 1);

    const float4* __restrict__ xv = (const float4*)x;
    const size_t row0 = ((size_t)b * IN_H + s ) * IN_W;
    const size_t row1 = ((size_t)b * IN_H + s1) * IN_W;

    const float4 v00 = __ldg(&xv[row0 + t ]);
    const float4 v01 = __ldg(&xv[row0 + t1]);
    const float4 v10 = __ldg(&xv[row1 + t ]);
    const float4 v11 = __ldg(&xv[row1 + t1]);

    // channels 0+1 share identical filters (reference quirk) -> pre-add
    float a[2][2] = { { v00.x + v00.y, v01.x + v01.y },
                      { v10.x + v10.y, v11.x + v11.y } };
    float zc[2][2] = { { v00.z, v01.z }, { v10.z, v11.z } };  // c2: (lpf, hpf)
    float wc[2][2] = { { v00.w, v01.w }, { v10.w, v11.w } };  // c3: (hpf, hpf)

    float out[2][2];
#pragma unroll
    for (int av = 0; av < 2; ++av) {
#pragma unroll
        for (int ah = 0; ah < 2; ++ah) {
            float acc = 0.0f;
#pragma unroll
            for (int dv = 0; dv < 2; ++dv) {
#pragma unroll
                for (int dh = 0; dh < 2; ++dh) {
                    acc = fmaf(L[av][dv] * L[ah][dh], a[dv][dh], acc);
                    acc = fmaf(L[av][dv] * G[ah][dh], zc[dv][dh], acc);
                    acc = fmaf(G[av][dv] * G[ah][dh], wc[dv][dh], acc);
                }
            }
            out[av][ah] = acc;
        }
    }

    const size_t ob = ((size_t)b * 1024 + 2 * s) * 1024 + 2 * t;
    float2* o0 = (float2*)(y + ob);
    float2* o1 = (float2*)(y + ob + 1024);
    *o0 = make_float2(out[0][0], out[0][1]);
    *o1 = make_float2(out[1][0], out[1][1]);
}

extern "C" void kernel_launch(void* const* d_in, const int* in_sizes, int n_in,
                              void* d_out, int out_size) {
    const float* x = (const float*)d_in[0];
    float* y = (float*)d_out;
    dim3 block(128, 1, 1);
    dim3 grid(IN_W / 128, IN_H, IN_B);
    idwt_db2_kernel<<<grid, block>>>(x, y);
}

// round 2
// speedup vs baseline: 1.0483x; 1.0483x over previous
#include <cuda_runtime.h>

// db2 inverse DWT (synthesis), polyphase form, 2 input cols per thread.
// x: [32, 512, 512, 4] NHWC f32  ->  y: [32, 1024, 1024, 1] f32

#define IN_H 512
#define IN_W 512
#define IN_B 32

// For input quad (v00 v01 / v10 v11) compute the 2x2 output block.
// Channels: (x+y) -> L(v)L(h), z -> L(v)G(h), w -> G(v)G(h).
__device__ __forceinline__ void quad2x2(
    const float4& v00, const float4& v01,
    const float4& v10, const float4& v11,
    const float L[2][2], const float G[2][2],
    float out[2][2])
{
    // horizontal pass: r_az[dv][ah] = L[ah][0]*a0 + L[ah][1]*a1 + G[ah][0]*z0 + G[ah][1]*z1
    //                  r_w [dv][ah] = G[ah][0]*w0 + G[ah][1]*w1
    float a0[2] = { v00.x + v00.y, v10.x + v10.y };
    float a1[2] = { v01.x + v01.y, v11.x + v11.y };
    float z0[2] = { v00.z, v10.z };
    float z1[2] = { v01.z, v11.z };
    float w0[2] = { v00.w, v10.w };
    float w1[2] = { v01.w, v11.w };

    float r_az[2][2], r_w[2][2];
#pragma unroll
    for (int dv = 0; dv < 2; ++dv) {
#pragma unroll
        for (int ah = 0; ah < 2; ++ah) {
            float r = L[ah][0] * a0[dv];
            r = fmaf(L[ah][1], a1[dv], r);
            r = fmaf(G[ah][0], z0[dv], r);
            r = fmaf(G[ah][1], z1[dv], r);
            r_az[dv][ah] = r;
            r_w[dv][ah] = fmaf(G[ah][0], w0[dv], G[ah][1] * w1[dv]);
        }
    }
    // vertical pass: out[av][ah] = sum_dv L[av][dv]*r_az[dv][ah] + G[av][dv]*r_w[dv][ah]
#pragma unroll
    for (int av = 0; av < 2; ++av) {
#pragma unroll
        for (int ah = 0; ah < 2; ++ah) {
            float r = L[av][0] * r_az[0][ah];
            r = fmaf(L[av][1], r_az[1][ah], r);
            r = fmaf(G[av][0], r_w[0][ah], r);
            r = fmaf(G[av][1], r_w[1][ah], r);
            out[av][ah] = r;
        }
    }
}

__global__ __launch_bounds__(128)
void idwt_db2_kernel(const float4* __restrict__ x, float4* __restrict__ y) {
    const int u = blockIdx.x * blockDim.x + threadIdx.x;   // 0..255 (col pair)
    const int s = blockIdx.y;                              // 0..511 (input row)
    const int b = blockIdx.z;                              // 0..31

    const float h0 = 0.48296291314469025f;
    const float h1 = 0.83651630373780790f;
    const float h2 = 0.22414386804185735f;
    const float h3 = -0.12940952255092145f;
    // lpf = {h3,h2,h1,h0} -> L[0]={h2,h0}, L[1]={h3,h1}
    // hpf = {-h0,h1,-h2,h3} -> G[0]={h1,h3}, G[1]={-h0,-h2}
    const float L[2][2] = { { h2,  h0 }, {  h3,  h1 } };
    const float G[2][2] = { { h1,  h3 }, { -h0, -h2 } };

    const int t0 = 2 * u;
    const int t1 = 2 * u + 1;
    const int t2 = min(2 * u + 2, IN_W - 1);
    const int s1 = min(s + 1, IN_H - 1);

    const size_t r0 = ((size_t)b * IN_H + s ) * IN_W;
    const size_t r1 = ((size_t)b * IN_H + s1) * IN_W;

    // 6 independent 16B loads, issued up front for max MLP
    const float4 A0 = __ldg(&x[r0 + t0]);
    const float4 A1 = __ldg(&x[r0 + t1]);
    const float4 A2 = __ldg(&x[r0 + t2]);
    const float4 B0 = __ldg(&x[r1 + t0]);
    const float4 B1 = __ldg(&x[r1 + t1]);
    const float4 B2 = __ldg(&x[r1 + t2]);

    float oA[2][2], oB[2][2];
    quad2x2(A0, A1, B0, B1, L, G, oA);   // input col t0 -> out cols 4u..4u+1
    quad2x2(A1, A2, B1, B2, L, G, oB);   // input col t1 -> out cols 4u+2..4u+3

    // output rows 2s, 2s+1 ; one float4 per row
    const size_t ob = ((size_t)b * 1024 + 2 * s) * 256 + u;
    y[ob]       = make_float4(oA[0][0], oA[0][1], oB[0][0], oB[0][1]);
    y[ob + 256] = make_float4(oA[1][0], oA[1][1], oB[1][0], oB[1][1]);
}

extern "C" void kernel_launch(void* const* d_in, const int* in_sizes, int n_in,
                              void* d_out, int out_size) {
    const float4* x = (const float4*)d_in[0];
    float4* y = (float4*)d_out;
    dim3 block(128, 1, 1);
    dim3 grid((IN_W / 2) / 128, IN_H, IN_B);
    idwt_db2_kernel<<<grid, block>>>(x, y);
}